// round 4
// baseline (speedup 1.0000x reference)
#include <cuda_runtime.h>
#include <stdint.h>

// EdgeFeaturizer: per-row 12 smallest of an 8192x8192 uniform distance matrix,
// then edge_index [n*k,2] + Gaussian RBF features [n*k,50].
// 2 rows per block; merged parallel tails.

#define N_ATOMS   8192
#define KNBR      12
#define NBINS     50
#define CAP       128           // per-row candidate cap (mean ~29 at t=0.0035)
#define THREADS   256
#define ROWS      2
#define T0        0.0035f

__device__ __forceinline__ void scan_row(const float4* __restrict__ rp, float t,
                                         unsigned long long* __restrict__ cand,
                                         int* __restrict__ cnt, int tid)
{
    #pragma unroll
    for (int half = 0; half < 2; half++) {
        const int i0 = tid + (half * 4 + 0) * THREADS;
        const int i1 = tid + (half * 4 + 1) * THREADS;
        const int i2 = tid + (half * 4 + 2) * THREADS;
        const int i3 = tid + (half * 4 + 3) * THREADS;
        float4 v0 = __ldcs(rp + i0);
        float4 v1 = __ldcs(rp + i1);
        float4 v2 = __ldcs(rp + i2);
        float4 v3 = __ldcs(rp + i3);

        float m0 = fminf(fminf(v0.x, v0.y), fminf(v0.z, v0.w));
        float m1 = fminf(fminf(v1.x, v1.y), fminf(v1.z, v1.w));
        float m2 = fminf(fminf(v2.x, v2.y), fminf(v2.z, v2.w));
        float m3 = fminf(fminf(v3.x, v3.y), fminf(v3.z, v3.w));
        float mn = fminf(fminf(m0, m1), fminf(m2, m3));
        if (mn < t) {                             // rare per-thread body
            #pragma unroll
            for (int j = 0; j < 4; j++) {
                float4 v = (j == 0) ? v0 : (j == 1) ? v1 : (j == 2) ? v2 : v3;
                int    i = (j == 0) ? i0 : (j == 1) ? i1 : (j == 2) ? i2 : i3;
                int h = (v.x < t) + (v.y < t) + (v.z < t) + (v.w < t);
                if (h) {
                    int p = atomicAdd(cnt, h);
                    unsigned base = 4u * (unsigned)i;
                    if (v.x < t && p < CAP)
                        cand[p++] = (((unsigned long long)__float_as_uint(v.x)) << 32) | (base + 0u);
                    if (v.y < t && p < CAP)
                        cand[p++] = (((unsigned long long)__float_as_uint(v.y)) << 32) | (base + 1u);
                    if (v.z < t && p < CAP)
                        cand[p++] = (((unsigned long long)__float_as_uint(v.z)) << 32) | (base + 2u);
                    if (v.w < t && p < CAP)
                        cand[p++] = (((unsigned long long)__float_as_uint(v.w)) << 32) | (base + 3u);
                }
            }
        }
    }
}

__global__ __launch_bounds__(THREADS, 6)
void edge_featurizer_kernel(const float* __restrict__ dm, float* __restrict__ out)
{
    __shared__ unsigned long long cand[ROWS][CAP];
    __shared__ int   s_cnt[ROWS];
    __shared__ float s_tc[NBINS];                // exp(-12.5 * c_j^2)
    __shared__ float s_d[ROWS][KNBR];
    __shared__ int   s_i[ROWS][KNBR];
    __shared__ float s_feat[ROWS][KNBR * NBINS];

    const int tid  = threadIdx.x;
    const int row0 = blockIdx.x * ROWS;

    if (tid < NBINS) {
        float c = (float)tid * (1.0f / 49.0f);
        s_tc[tid] = __expf(-12.5f * c * c);
    }
    if (tid < ROWS) s_cnt[tid] = 0;
    __syncthreads();

    // ---- Phase 1: scan both rows back-to-back (disjoint shared state) ----
    const float4* rp0 = reinterpret_cast<const float4*>(dm + (size_t)(row0 + 0) * N_ATOMS);
    const float4* rp1 = reinterpret_cast<const float4*>(dm + (size_t)(row0 + 1) * N_ATOMS);
    scan_row(rp0, T0, cand[0], &s_cnt[0], tid);
    scan_row(rp1, T0, cand[1], &s_cnt[1], tid);
    __syncthreads();

    // ---- Rare exact fallback, per row (block-uniform control flow) ----
    #pragma unroll
    for (int r = 0; r < ROWS; r++) {
        int c = s_cnt[r];
        float t = T0;
        while (c < KNBR || c > CAP) {
            t = (c < KNBR) ? t * 8.0f : t * 0.25f;
            __syncthreads();
            if (tid == 0) s_cnt[r] = 0;
            __syncthreads();
            const float4* rp = reinterpret_cast<const float4*>(
                dm + (size_t)(row0 + r) * N_ATOMS);
            scan_row(rp, t, cand[r], &s_cnt[r], tid);
            __syncthreads();
            c = s_cnt[r];
        }
    }

    // ---- Phase 2: parallel rank selection, both rows concurrently ----
    {
        const int r  = tid >> 7;                  // 0 or 1
        const int lt = tid & 127;
        const int c  = s_cnt[r];
        if (lt < c) {
            unsigned long long mine = cand[r][lt];
            int rank = 0;
            int j = 0;
            for (; j + 4 <= c; j += 4) {
                rank += (cand[r][j + 0] < mine);
                rank += (cand[r][j + 1] < mine);
                rank += (cand[r][j + 2] < mine);
                rank += (cand[r][j + 3] < mine);
            }
            for (; j < c; j++) rank += (cand[r][j] < mine);
            if (rank < KNBR) {
                s_d[r][rank] = __uint_as_float((unsigned)(mine >> 32));
                s_i[r][rank] = (int)(mine & 0xffffffffu);
            }
        }
    }
    __syncthreads();

    // ---- Phase 3: features via geometric recurrence, both rows concurrently ----
    // exp(-12.5 (d-c_j)^2) = exp(-12.5 d^2) * r^j * exp(-12.5 c_j^2), r = exp(25d/49)
    {
        const int r  = tid >> 7;
        const int lt = tid & 127;
        if (lt < KNBR) {
            float d  = s_d[r][lt];
            float e0 = __expf(-12.5f * d * d);
            float g  = __expf((25.0f / 49.0f) * d);
            float p  = e0;
            #pragma unroll
            for (int j = 0; j < NBINS; j++) {
                s_feat[r][lt * NBINS + j] = p * s_tc[j];
                p *= g;
            }
            size_t eo = (size_t)(row0 + r) * (2 * KNBR) + 2 * lt;
            out[eo]     = (float)(row0 + r);
            out[eo + 1] = (float)s_i[r][lt];
        }
    }
    __syncthreads();

    // ---- Phase 4: contiguous coalesced writeback (1200 floats) ----
    float* __restrict__ outF = out + (size_t)N_ATOMS * KNBR * 2
                                   + (size_t)row0 * (KNBR * NBINS);
    const float* sf = &s_feat[0][0];
    #pragma unroll
    for (int i = tid; i < ROWS * KNBR * NBINS; i += THREADS)
        outF[i] = sf[i];
}

extern "C" void kernel_launch(void* const* d_in, const int* in_sizes, int n_in,
                              void* d_out, int out_size)
{
    (void)in_sizes; (void)n_in; (void)out_size;
    const float* dm = (const float*)d_in[0];
    float* out = (float*)d_out;
    edge_featurizer_kernel<<<N_ATOMS / ROWS, THREADS>>>(dm, out);
}

// round 5
// speedup vs baseline: 1.0916x; 1.0916x over previous
#include <cuda_runtime.h>
#include <stdint.h>

// EdgeFeaturizer: per-row 12 smallest of an 8192x8192 uniform distance matrix,
// then edge_index [n*k,2] + Gaussian RBF features [n*k,50].
// R5: cp.async.bulk (TMA-path) row staging into SMEM; scan from SMEM.

#define N_ATOMS   8192
#define KNBR      12
#define NBINS     50
#define CAP       192
#define THREADS   256
#define T0        0.0035f
#define CHUNKS    4
#define CHUNK_F   2048          // floats per chunk (8 KB)
#define CHUNK_V   512           // float4 per chunk

__device__ __forceinline__ unsigned smem_u32(const void* p) {
    return (unsigned)__cvta_generic_to_shared(p);
}

__device__ __forceinline__ void mbar_wait(unsigned mb, unsigned parity) {
    unsigned done;
    asm volatile(
        "{\n\t.reg .pred p;\n\t"
        "mbarrier.try_wait.parity.acquire.cta.shared::cta.b64 p, [%1], %2;\n\t"
        "selp.b32 %0, 1, 0, p;\n\t}"
        : "=r"(done) : "r"(mb), "r"(parity) : "memory");
    if (!done) {
        asm volatile(
            "{\n\t.reg .pred P1;\n\t"
            "WL_%=:\n\t"
            "mbarrier.try_wait.parity.acquire.cta.shared::cta.b64 P1, [%0], %1, 0x989680;\n\t"
            "@P1 bra.uni WD_%=;\n\t"
            "bra.uni WL_%=;\n\t"
            "WD_%=:\n\t}"
            :: "r"(mb), "r"(parity) : "memory");
    }
}

__global__ __launch_bounds__(THREADS, 6)
void edge_featurizer_kernel(const float* __restrict__ dm, float* __restrict__ out)
{
    __shared__ __align__(128) float s_row[N_ATOMS];     // 32 KB row stage
    __shared__ unsigned long long cand[CAP];
    __shared__ int   s_cnt;
    __shared__ float s_tc[NBINS];
    __shared__ float s_d[KNBR];
    __shared__ int   s_i[KNBR];
    __shared__ float s_feat[KNBR * NBINS];
    __shared__ __align__(8) unsigned long long s_mbar[CHUNKS];

    const int tid = threadIdx.x;
    const int row = blockIdx.x;

    if (tid < NBINS) {
        float c = (float)tid * (1.0f / 49.0f);
        s_tc[tid] = __expf(-12.5f * c * c);
    }
    if (tid == 0) {
        s_cnt = 0;
        #pragma unroll
        for (int c = 0; c < CHUNKS; c++) {
            unsigned mb = smem_u32(&s_mbar[c]);
            asm volatile("mbarrier.init.shared.b64 [%0], %1;"
                         :: "r"(mb), "r"(1) : "memory");
        }
    }
    __syncthreads();

    // ---- issue all 4 bulk copies up front (TMA path, zero LDG pressure) ----
    if (tid == 0) {
        const char* src = (const char*)(dm + (size_t)row * N_ATOMS);
        #pragma unroll
        for (int c = 0; c < CHUNKS; c++) {
            unsigned mb  = smem_u32(&s_mbar[c]);
            unsigned dst = smem_u32(&s_row[c * CHUNK_F]);
            asm volatile("mbarrier.arrive.expect_tx.shared.b64 _, [%0], %1;"
                         :: "r"(mb), "r"(CHUNK_F * 4) : "memory");
            asm volatile(
                "cp.async.bulk.shared::cta.global.mbarrier::complete_tx::bytes "
                "[%0], [%1], %2, [%3];"
                :: "r"(dst), "l"(src + (size_t)c * CHUNK_F * 4),
                   "r"(CHUNK_F * 4), "r"(mb) : "memory");
        }
    }

    const float4* s4 = reinterpret_cast<const float4*>(s_row);

    // ---- Phase 1: chunk-pipelined scan from SMEM ----
    #pragma unroll
    for (int c = 0; c < CHUNKS; c++) {
        mbar_wait(smem_u32(&s_mbar[c]), 0);
        const int i0 = c * CHUNK_V + tid;
        const int i1 = i0 + THREADS;
        float4 v0 = s4[i0];
        float4 v1 = s4[i1];
        float m0 = fminf(fminf(v0.x, v0.y), fminf(v0.z, v0.w));
        float m1 = fminf(fminf(v1.x, v1.y), fminf(v1.z, v1.w));
        if (fminf(m0, m1) < T0) {                     // rare per-thread body
            #pragma unroll
            for (int j = 0; j < 2; j++) {
                float4 v = (j == 0) ? v0 : v1;
                int    i = (j == 0) ? i0 : i1;
                int h = (v.x < T0) + (v.y < T0) + (v.z < T0) + (v.w < T0);
                if (h) {
                    int p = atomicAdd(&s_cnt, h);
                    unsigned base = 4u * (unsigned)i;
                    if (v.x < T0 && p < CAP)
                        cand[p++] = (((unsigned long long)__float_as_uint(v.x)) << 32) | (base + 0u);
                    if (v.y < T0 && p < CAP)
                        cand[p++] = (((unsigned long long)__float_as_uint(v.y)) << 32) | (base + 1u);
                    if (v.z < T0 && p < CAP)
                        cand[p++] = (((unsigned long long)__float_as_uint(v.z)) << 32) | (base + 2u);
                    if (v.w < T0 && p < CAP)
                        cand[p++] = (((unsigned long long)__float_as_uint(v.w)) << 32) | (base + 3u);
                }
            }
        }
    }
    __syncthreads();

    // ---- exact fallback: rescan from SMEM with adjusted t (rare) ----
    int c = s_cnt;
    float t = T0;
    while (c < KNBR || c > CAP) {
        t = (c < KNBR) ? t * 8.0f : t * 0.25f;
        __syncthreads();
        if (tid == 0) s_cnt = 0;
        __syncthreads();
        #pragma unroll
        for (int ii = 0; ii < N_ATOMS / 4 / THREADS; ii++) {
            int i = tid + ii * THREADS;
            float4 v = s4[i];
            if (fminf(fminf(v.x, v.y), fminf(v.z, v.w)) < t) {
                int h = (v.x < t) + (v.y < t) + (v.z < t) + (v.w < t);
                int p = atomicAdd(&s_cnt, h);
                unsigned base = 4u * (unsigned)i;
                if (v.x < t && p < CAP)
                    cand[p++] = (((unsigned long long)__float_as_uint(v.x)) << 32) | (base + 0u);
                if (v.y < t && p < CAP)
                    cand[p++] = (((unsigned long long)__float_as_uint(v.y)) << 32) | (base + 1u);
                if (v.z < t && p < CAP)
                    cand[p++] = (((unsigned long long)__float_as_uint(v.z)) << 32) | (base + 2u);
                if (v.w < t && p < CAP)
                    cand[p++] = (((unsigned long long)__float_as_uint(v.w)) << 32) | (base + 3u);
            }
        }
        __syncthreads();
        c = s_cnt;
        __syncthreads();
    }

    // ---- Phase 2: parallel rank selection (keys unique -> ranks distinct) ----
    if (tid < c) {
        unsigned long long mine = cand[tid];
        int rank = 0;
        int j = 0;
        for (; j + 4 <= c; j += 4) {
            rank += (cand[j + 0] < mine);
            rank += (cand[j + 1] < mine);
            rank += (cand[j + 2] < mine);
            rank += (cand[j + 3] < mine);
        }
        for (; j < c; j++) rank += (cand[j] < mine);
        if (rank < KNBR) {
            s_d[rank] = __uint_as_float((unsigned)(mine >> 32));
            s_i[rank] = (int)(mine & 0xffffffffu);
        }
    }
    __syncthreads();

    // ---- Phase 3: features via geometric recurrence (2 MUFU per edge) ----
    if (tid < KNBR) {
        float d  = s_d[tid];
        float e0 = __expf(-12.5f * d * d);
        float g  = __expf((25.0f / 49.0f) * d);
        float p  = e0;
        #pragma unroll
        for (int j = 0; j < NBINS; j++) {
            s_feat[tid * NBINS + j] = p * s_tc[j];
            p *= g;
        }
        size_t eo = (size_t)row * (2 * KNBR) + 2 * tid;
        out[eo]     = (float)row;
        out[eo + 1] = (float)s_i[tid];
    }
    __syncthreads();

    // ---- Phase 4: coalesced feature writeback ----
    float* __restrict__ outF = out + (size_t)N_ATOMS * KNBR * 2
                                   + (size_t)row * (KNBR * NBINS);
    #pragma unroll
    for (int i = tid; i < KNBR * NBINS; i += THREADS)
        outF[i] = s_feat[i];
}

extern "C" void kernel_launch(void* const* d_in, const int* in_sizes, int n_in,
                              void* d_out, int out_size)
{
    (void)in_sizes; (void)n_in; (void)out_size;
    const float* dm = (const float*)d_in[0];
    float* out = (float*)d_out;
    edge_featurizer_kernel<<<N_ATOMS, THREADS>>>(dm, out);
}